// round 8
// baseline (speedup 1.0000x reference)
#include <cuda_runtime.h>
#include <cuda_bf16.h>
#include <mma.h>
#include <math.h>
#include <stdint.h>

using namespace nvcuda;

#define B_   4
#define NO_  64
#define DO_  13
#define H_   256
#define NP_  32768

__device__ float g_Anorm[B_*NO_*NO_];
__device__ float g_mobj [B_*NO_*DO_];
__device__ float g_objM [B_*NO_*12];
__device__ __nv_bfloat16 g_W1h[H_*H_];
__device__ __nv_bfloat16 g_W1l[H_*H_];

__device__ __forceinline__ float gelu_exact(float x) {
    return 0.5f * x * (1.0f + erff(x * 0.7071067811865476f));
}
__device__ __forceinline__ void ffma2(unsigned long long& a,
                                      unsigned long long x,
                                      unsigned long long w) {
    asm("fma.rn.f32x2 %0, %1, %2, %0;" : "+l"(a) : "l"(x), "l"(w));
}
__device__ __forceinline__ unsigned long long pack2(float lo, float hi) {
    unsigned long long r;
    asm("mov.b64 %0, {%1, %2};" : "=l"(r) : "f"(lo), "f"(hi));
    return r;
}
__device__ __forceinline__ void unpack2(unsigned long long v, float& lo, float& hi) {
    asm("mov.b64 {%0, %1}, %2;" : "=f"(lo), "=f"(hi) : "l"(v));
}
__device__ __forceinline__ void split2(float a, __nv_bfloat16& h, __nv_bfloat16& l) {
    h = __float2bfloat16(a);
    l = __float2bfloat16(a - __bfloat162float(h));
}

// ---------------------------------------------------------------------------
// K1: preconvert W1 -> bf16 hi/lo
// ---------------------------------------------------------------------------
__global__ void k1_convert(const float* __restrict__ W1,
                           __nv_bfloat16* __restrict__ Wh,
                           __nv_bfloat16* __restrict__ Wl) {
    int idx = blockIdx.x * blockDim.x + threadIdx.x;
    if (idx < H_*H_) {
        float v = W1[idx];
        __nv_bfloat16 h, l; split2(v, h, l);
        Wh[idx] = h; Wl[idx] = l;
    }
}

// ---------------------------------------------------------------------------
// K0: adjacency + rigid-body precompute + dx_o cols [0:3],[6:10]
// ---------------------------------------------------------------------------
__global__ void k0_obj_prep(const float* __restrict__ xo,
                            float* __restrict__ Anorm,
                            float* __restrict__ objM,
                            float* __restrict__ dxo) {
    int b = blockIdx.x;
    int i = threadIdx.x;
    __shared__ float pos[NO_][3];

    const float* xrow = xo + (b*NO_ + i)*DO_;
    float x[13];
#pragma unroll
    for (int k = 0; k < 13; k++) x[k] = xrow[k];
    pos[i][0] = x[0]; pos[i][1] = x[1]; pos[i][2] = x[2];
    __syncthreads();

    const float s2 = 0.3f * 0.3f;
    float rs = 0.0f;
    for (int j = 0; j < NO_; j++) {
        float dx = x[0]-pos[j][0], dy = x[1]-pos[j][1], dz = x[2]-pos[j][2];
        float d2 = dx*dx + dy*dy + dz*dz;
        float v = (j == i) ? 1.0f : expf(-d2 / s2);
        rs += v;
    }
    for (int j = 0; j < NO_; j++) {
        float dx = x[0]-pos[j][0], dy = x[1]-pos[j][1], dz = x[2]-pos[j][2];
        float d2 = dx*dx + dy*dy + dz*dz;
        float v = (j == i) ? 1.0f : expf(-d2 / s2);
        Anorm[(b*NO_ + i)*NO_ + j] = v / rs;
    }

    float w = x[6], ux = x[7], uy = x[8], uz = x[9];
    float ox = x[10], oy = x[11], oz = x[12];
    float ss = w*w - (ux*ux + uy*uy + uz*uz);
    float R00 = ss + 2.0f*ux*ux,        R01 = 2.0f*(ux*uy - w*uz), R02 = 2.0f*(ux*uz + w*uy);
    float R10 = 2.0f*(ux*uy + w*uz),    R11 = ss + 2.0f*uy*uy,     R12 = 2.0f*(uy*uz - w*ux);
    float R20 = 2.0f*(ux*uz - w*uy),    R21 = 2.0f*(uy*uz + w*ux), R22 = ss + 2.0f*uz*uz;
    float M00 = -oz*R10 + oy*R20, M01 = -oz*R11 + oy*R21, M02 = -oz*R12 + oy*R22;
    float M10 =  oz*R00 - ox*R20, M11 =  oz*R01 - ox*R21, M12 =  oz*R02 - ox*R22;
    float M20 = -oy*R00 + ox*R10, M21 = -oy*R01 + ox*R11, M22 = -oy*R02 + ox*R12;
    float c0 = x[3] - (M00*x[0] + M01*x[1] + M02*x[2]);
    float c1 = x[4] - (M10*x[0] + M11*x[1] + M12*x[2]);
    float c2 = x[5] - (M20*x[0] + M21*x[1] + M22*x[2]);

    float* om = objM + (b*NO_ + i)*12;
    om[0]=c0; om[1]=c1; om[2]=c2;
    om[3]=M00; om[4]=M01; om[5]=M02;
    om[6]=M10; om[7]=M11; om[8]=M12;
    om[9]=M20; om[10]=M21; om[11]=M22;

    float* orow = dxo + (b*NO_ + i)*DO_;
    orow[0] = x[3]; orow[1] = x[4]; orow[2] = x[5];
    float qw = x[6], qx = x[7], qy = x[8], qz = x[9];
    orow[6] = 0.5f * (-(ox*qx + oy*qy + oz*qz));
    orow[7] = 0.5f * ( ox*qw + oy*qz - oz*qy);
    orow[8] = 0.5f * (-ox*qz + oy*qw + oz*qx);
    orow[9] = 0.5f * ( ox*qy - oy*qx + oz*qw);
}

// ---------------------------------------------------------------------------
// K2: edge MLP.  Layer-0 SIMT (register-tiled FFMA2); layer-1 wmma bf16x3.
// One block per node: M = 64 edges.  grid = B*NO = 256, block = 256 (8 warps).
// ---------------------------------------------------------------------------
#define EPAD 68
#define SCR  260   // scratch row stride (floats)

// smem byte offsets
#define OFF_SCRATCH 0                        // 64*260*4 = 66560
#define OFF_AH      66560                    // 64*256*2 = 32768
#define OFF_AL      99328                    // 32768
#define OFF_XOS     132096                   // 832*4 = 3328
#define OFF_EIN     135424                   // 2108*4 = 8432
#define OFF_AROW    143856                   // 64*4
#define OFF_B1S     144112                   // 256*4
#define OFF_RED2    145136                   // 104*4 = 416
#define K2_SMEM     145552

__global__ void __launch_bounds__(256)
k2_edge(const float* __restrict__ xo, const float* __restrict__ tptr,
        const float* __restrict__ Anorm,
        const float* __restrict__ W0, const float* __restrict__ b0,
        const __nv_bfloat16* __restrict__ W1h, const __nv_bfloat16* __restrict__ W1l,
        const float* __restrict__ b1,
        const float* __restrict__ W2, const float* __restrict__ b2,
        float* __restrict__ mobj) {
    extern __shared__ __align__(16) char dsm[];
    float* scratch = (float*)(dsm + OFF_SCRATCH);
    __nv_bfloat16* Ah = (__nv_bfloat16*)(dsm + OFF_AH);
    __nv_bfloat16* Al = (__nv_bfloat16*)(dsm + OFF_AL);
    float* xo_s = (float*)(dsm + OFF_XOS);
    float* einT = (float*)(dsm + OFF_EIN);
    float* Arow = (float*)(dsm + OFF_AROW);
    float* b1s  = (float*)(dsm + OFF_B1S);
    float* red2 = (float*)(dsm + OFF_RED2);

    int tid = threadIdx.x;
    int wid = tid >> 5, lane = tid & 31;
    int blk = blockIdx.x;
    int b = blk >> 6, i = blk & 63;

    const float* xb = xo + b*NO_*DO_;
    for (int idx = tid; idx < NO_*DO_; idx += 256) xo_s[idx] = xb[idx];
    if (tid < 64) Arow[tid] = Anorm[(b*NO_ + i)*NO_ + tid];
    for (int idx = tid; idx < 256; idx += 256) b1s[idx] = b1[idx];
    __syncthreads();

    float t = *tptr;
    float xi0 = xo_s[i*13+0], xi1 = xo_s[i*13+1], xi2 = xo_s[i*13+2];
    for (int idx = tid; idx < 31*64; idx += 256) {
        int k = idx >> 6, j = idx & 63;
        float v;
        if (k < 13) v = xo_s[i*13 + k];
        else if (k < 26) v = xo_s[j*13 + (k-13)];
        else if (k < 29) v = xo_s[j*13 + (k-26)] - xo_s[i*13 + (k-26)];
        else if (k == 29) {
            float dx = xo_s[j*13+0]-xi0, dy = xo_s[j*13+1]-xi1, dz = xo_s[j*13+2]-xi2;
            v = sqrtf(dx*dx + dy*dy + dz*dz);
        } else v = t;
        einT[k*EPAD + j] = v;
    }
    __syncthreads();

    // ---- layer 0 (SIMT register tile 8 edges x 8 channels) ----
    {
        int ct = tid & 31;       // channels ct + 32q
        int e0 = (tid >> 5) * 8; // 8 edges
        unsigned long long acc2[32];
        unsigned long long bb2[4];
#pragma unroll
        for (int p = 0; p < 4; p++) bb2[p] = pack2(b0[ct + 64*p], b0[ct + 64*p + 32]);
#pragma unroll
        for (int e = 0; e < 8; e++)
#pragma unroll
            for (int p = 0; p < 4; p++) acc2[e*4+p] = bb2[p];

        for (int k = 0; k < 31; k++) {
            const float* wr = W0 + k*H_;
            unsigned long long w2[4];
#pragma unroll
            for (int p = 0; p < 4; p++) w2[p] = pack2(wr[ct + 64*p], wr[ct + 64*p + 32]);
            float4 a0v = *reinterpret_cast<const float4*>(&einT[k*EPAD + e0]);
            float4 a1v = *reinterpret_cast<const float4*>(&einT[k*EPAD + e0 + 4]);
            float av[8] = {a0v.x,a0v.y,a0v.z,a0v.w,a1v.x,a1v.y,a1v.z,a1v.w};
#pragma unroll
            for (int e = 0; e < 8; e++) {
                unsigned long long s2 = pack2(av[e], av[e]);
#pragma unroll
                for (int p = 0; p < 4; p++) ffma2(acc2[e*4+p], w2[p], s2);
            }
        }
        // gelu + split -> Ah/Al [edge][channel]
#pragma unroll
        for (int e = 0; e < 8; e++) {
            int row = (e0 + e) * 256;
#pragma unroll
            for (int p = 0; p < 4; p++) {
                float lo, hi; unpack2(acc2[e*4+p], lo, hi);
                float g0 = gelu_exact(lo), g1 = gelu_exact(hi);
                __nv_bfloat16 h, l;
                split2(g0, h, l);
                Ah[row + ct + 64*p] = h;       Al[row + ct + 64*p] = l;
                split2(g1, h, l);
                Ah[row + ct + 64*p + 32] = h;  Al[row + ct + 64*p + 32] = l;
            }
        }
    }
    __syncthreads();

    // ---- layer 1 (wmma bf16x3): [64x256] @ [256x256] -> scratch fp32 ----
    {
        int mtile = wid & 3;       // 16-row tile
        int nh = wid >> 1 & 0;     // placeholder (computed below)
        nh = wid >> 2;             // N-half: 0 or 1
        wmma::fragment<wmma::accumulator, 16, 16, 16, float> acc[8];
#pragma unroll
        for (int nf = 0; nf < 8; nf++) wmma::fill_fragment(acc[nf], 0.0f);

        for (int kt = 0; kt < 16; kt++) {
            wmma::fragment<wmma::matrix_a, 16, 16, 16, __nv_bfloat16, wmma::row_major> fah, fal;
            wmma::load_matrix_sync(fah, Ah + (mtile*16)*256 + kt*16, 256);
            wmma::load_matrix_sync(fal, Al + (mtile*16)*256 + kt*16, 256);
#pragma unroll
            for (int nf = 0; nf < 8; nf++) {
                int col0 = nh*128 + nf*16;
                wmma::fragment<wmma::matrix_b, 16, 16, 16, __nv_bfloat16, wmma::row_major> fbh, fbl;
                wmma::load_matrix_sync(fbh, W1h + (kt*16)*H_ + col0, H_);
                wmma::load_matrix_sync(fbl, W1l + (kt*16)*H_ + col0, H_);
                wmma::mma_sync(acc[nf], fah, fbh, acc[nf]);
                wmma::mma_sync(acc[nf], fah, fbl, acc[nf]);
                wmma::mma_sync(acc[nf], fal, fbh, acc[nf]);
            }
        }
#pragma unroll
        for (int nf = 0; nf < 8; nf++)
            wmma::store_matrix_sync(&scratch[(mtile*16)*SCR + nh*128 + nf*16],
                                    acc[nf], SCR, wmma::mem_row_major);
    }
    __syncthreads();

    // ---- epilogue: u[c] = sum_e Arow[e] * gelu(scratch[e][c] + b1[c]) ----
    {
        int c = tid;
        float bc = b1s[c];
        float u = 0.0f;
#pragma unroll 8
        for (int e = 0; e < 64; e++)
            u += Arow[e] * gelu_exact(scratch[e*SCR + c] + bc);

        float vd[13];
#pragma unroll
        for (int d = 0; d < 13; d++) vd[d] = u * W2[c*13 + d];
#pragma unroll
        for (int off = 16; off > 0; off >>= 1)
#pragma unroll
            for (int d = 0; d < 13; d++) vd[d] += __shfl_down_sync(0xffffffffu, vd[d], off);
        if (lane == 0)
#pragma unroll
            for (int d = 0; d < 13; d++) red2[wid*13 + d] = vd[d];
    }
    __syncthreads();
    if (tid < 13) {
        float s = b2[tid];
#pragma unroll
        for (int wp = 0; wp < 8; wp++) s += red2[wp*13 + tid];
        mobj[(b*NO_ + i)*13 + tid] = s;
    }
}

// ---------------------------------------------------------------------------
// K3: both node MLPs, 4 rows/block, grid = 128
// ---------------------------------------------------------------------------
__global__ void __launch_bounds__(256)
k3_node(const float* __restrict__ xo, const float* __restrict__ mobj,
        const float* __restrict__ tptr,
        const float* __restrict__ vw0, const float* __restrict__ vb0,
        const float* __restrict__ vw1, const float* __restrict__ vb1,
        const float* __restrict__ vw2, const float* __restrict__ vb2,
        const float* __restrict__ vw3, const float* __restrict__ vb3,
        const float* __restrict__ ow0, const float* __restrict__ ob0,
        const float* __restrict__ ow1, const float* __restrict__ ob1,
        const float* __restrict__ ow2, const float* __restrict__ ob2,
        const float* __restrict__ ow3, const float* __restrict__ ob3,
        float* __restrict__ dxo) {
    __shared__ __align__(16) float inT[27*4];
    __shared__ __align__(16) float hA[256*4];
    __shared__ __align__(16) float hB[256*4];

    int tid = threadIdx.x;
    int mlp = blockIdx.x >> 6;
    int rem = blockIdx.x & 63;
    int b = rem >> 4, grp = rem & 15;
    int i0 = grp * 4;

    const float *W0, *B0, *W1, *B1, *W2, *B2, *W3, *B3;
    int col0;
    if (mlp == 0) { W0=vw0; B0=vb0; W1=vw1; B1=vb1; W2=vw2; B2=vb2; W3=vw3; B3=vb3; col0 = 3; }
    else          { W0=ow0; B0=ob0; W1=ow1; B1=ob1; W2=ow2; B2=ob2; W3=ow3; B3=ob3; col0 = 10; }

    float t = *tptr;
    for (int idx = tid; idx < 27*4; idx += 256) {
        int k = idx >> 2, r = idx & 3;
        int row = b*NO_ + i0 + r;
        float v;
        if (k < 13) v = xo[row*13 + k];
        else if (k < 26) v = mobj[row*13 + (k-13)];
        else v = t;
        inT[k*4 + r] = v;
    }
    __syncthreads();

    unsigned long long acc2[2];
    float av[4];

    {
        float bb = B0[tid];
        unsigned long long bb2 = pack2(bb, bb);
        acc2[0]=bb2; acc2[1]=bb2;
#pragma unroll
        for (int k = 0; k < 27; k++) {
            float w = W0[k*H_ + tid];
            unsigned long long w2 = pack2(w, w);
            ulonglong2 pq = *reinterpret_cast<const ulonglong2*>(&inT[k*4]);
            ffma2(acc2[0], pq.x, w2);
            ffma2(acc2[1], pq.y, w2);
        }
        unpack2(acc2[0], av[0], av[1]); unpack2(acc2[1], av[2], av[3]);
#pragma unroll
        for (int r = 0; r < 4; r++) hA[tid*4 + r] = gelu_exact(av[r]);
    }
    __syncthreads();

#define K3_LAYER256(W, BV, SRC, DST)                                           \
    {                                                                          \
        float bb = BV[tid];                                                    \
        unsigned long long bb2 = pack2(bb, bb);                                \
        acc2[0]=bb2; acc2[1]=bb2;                                              \
        for (int k0 = 0; k0 < 256; k0 += 8) {                                  \
            _Pragma("unroll")                                                  \
            for (int p = 0; p < 8; p++) {                                      \
                float w = W[(k0+p)*H_ + tid];                                  \
                unsigned long long w2 = pack2(w, w);                           \
                ulonglong2 pq = *reinterpret_cast<const ulonglong2*>(&SRC[(k0+p)*4]); \
                ffma2(acc2[0], pq.x, w2);                                      \
                ffma2(acc2[1], pq.y, w2);                                      \
            }                                                                  \
        }                                                                      \
        unpack2(acc2[0], av[0], av[1]); unpack2(acc2[1], av[2], av[3]);        \
        _Pragma("unroll")                                                      \
        for (int r = 0; r < 4; r++) DST[tid*4 + r] = gelu_exact(av[r]);        \
    }                                                                          \
    __syncthreads();

    K3_LAYER256(W1, B1, hA, hB)
    K3_LAYER256(W2, B2, hB, hA)

    {
        int wp = tid >> 5, lane = tid & 31;
        if (wp < 4) {
            float p0 = 0.0f, p1 = 0.0f, p2 = 0.0f;
#pragma unroll
            for (int k = lane; k < 256; k += 32) {
                float h = hA[k*4 + wp];
                p0 += h * W3[k*3 + 0];
                p1 += h * W3[k*3 + 1];
                p2 += h * W3[k*3 + 2];
            }
#pragma unroll
            for (int off = 16; off > 0; off >>= 1) {
                p0 += __shfl_down_sync(0xffffffffu, p0, off);
                p1 += __shfl_down_sync(0xffffffffu, p1, off);
                p2 += __shfl_down_sync(0xffffffffu, p2, off);
            }
            if (lane == 0) {
                int row = b*NO_ + i0 + wp;
                dxo[row*13 + col0 + 0] = p0 + B3[0];
                dxo[row*13 + col0 + 1] = p1 + B3[1];
                dxo[row*13 + col0 + 2] = p2 + B3[2];
            }
        }
    }
}

// ---------------------------------------------------------------------------
// K4: particle update
// ---------------------------------------------------------------------------
#define PPB  256
#define SPAD 36

__global__ void __launch_bounds__(256)
k4_particles(const float* __restrict__ xp, const float* __restrict__ S,
             const float* __restrict__ objM, float* __restrict__ dxp) {
    extern __shared__ float sm[];
    float* Ms  = sm;
    float* Ssm = sm + 768;

    int tid = threadIdx.x;
    int b = blockIdx.y;
    int n0 = blockIdx.x * PPB;

    for (int idx = tid; idx < NO_*12; idx += 256) Ms[idx] = objM[b*NO_*12 + idx];

    int n = n0 + tid;
    const float* xr = xp + ((long)b*NP_ + n)*13;
    float px = xr[10], py = xr[11], pz = xr[12];
    float cvx = xr[3], cvy = xr[4], cvz = xr[5];

    unsigned long long acc2[6];
#pragma unroll
    for (int j = 0; j < 6; j++) acc2[j] = 0ull;

    const float* Sbase = S + ((long)b*NP_ + n0)*NO_;

    for (int c = 0; c < 2; c++) {
        __syncthreads();
        {
            const float4* src = reinterpret_cast<const float4*>(Sbase + c*32);
#pragma unroll
            for (int k = 0; k < 8; k++) {
                int idx = k*256 + tid;
                int p = idx >> 3, j = idx & 7;
                float4 v = src[p*16 + j];
                *reinterpret_cast<float4*>(&Ssm[p*SPAD + j*4]) = v;
            }
        }
        __syncthreads();

        const float4* srow = reinterpret_cast<const float4*>(&Ssm[tid*SPAD]);
#pragma unroll
        for (int m4 = 0; m4 < 8; m4++) {
            float4 s4 = srow[m4];
#pragma unroll
            for (int e = 0; e < 4; e++) {
                int m = c*32 + m4*4 + e;
                float s = (e==0) ? s4.x : (e==1) ? s4.y : (e==2) ? s4.z : s4.w;
                unsigned long long s2v = pack2(s, s);
                const ulonglong2* mr = reinterpret_cast<const ulonglong2*>(Ms + m*12);
                ulonglong2 m0 = mr[0], m1 = mr[1], m2 = mr[2];
                ffma2(acc2[0], m0.x, s2v); ffma2(acc2[1], m0.y, s2v);
                ffma2(acc2[2], m1.x, s2v); ffma2(acc2[3], m1.y, s2v);
                ffma2(acc2[4], m2.x, s2v); ffma2(acc2[5], m2.y, s2v);
            }
        }
    }

    float a0,a1,a2,a3,a4,a5,a6,a7,a8,a9,a10,a11;
    unpack2(acc2[0], a0, a1);  unpack2(acc2[1], a2, a3);
    unpack2(acc2[2], a4, a5);  unpack2(acc2[3], a6, a7);
    unpack2(acc2[4], a8, a9);  unpack2(acc2[5], a10, a11);
    float f0 = a0 + a3*px + a4*py + a5*pz;
    float f1 = a1 + a6*px + a7*py + a8*pz;
    float f2 = a2 + a9*px + a10*py + a11*pz;

    __syncthreads();
    float* orow = &Ssm[tid*13];
    orow[0] = f0; orow[1] = f1; orow[2] = f2;
    orow[3] = f0 - cvx; orow[4] = f1 - cvy; orow[5] = f2 - cvz;
#pragma unroll
    for (int d = 6; d < 13; d++) orow[d] = 0.0f;
    __syncthreads();

    float* og = dxp + ((long)b*NP_ + n0)*13;
    for (int idx = tid; idx < PPB*13; idx += 256) og[idx] = Ssm[idx];
}

// ---------------------------------------------------------------------------
extern "C" void kernel_launch(void* const* d_in, const int* in_sizes, int n_in,
                              void* d_out, int out_size) {
    const float* t   = (const float*)d_in[0];
    const float* x_p = (const float*)d_in[1];
    const float* x_o = (const float*)d_in[2];
    const float* S   = (const float*)d_in[3];
    const float* ew0 = (const float*)d_in[4];  const float* eb0 = (const float*)d_in[5];
    const float* ew1 = (const float*)d_in[6];  const float* eb1 = (const float*)d_in[7];
    const float* ew2 = (const float*)d_in[8];  const float* eb2 = (const float*)d_in[9];
    const float* vw0 = (const float*)d_in[10]; const float* vb0 = (const float*)d_in[11];
    const float* vw1 = (const float*)d_in[12]; const float* vb1 = (const float*)d_in[13];
    const float* vw2 = (const float*)d_in[14]; const float* vb2 = (const float*)d_in[15];
    const float* vw3 = (const float*)d_in[16]; const float* vb3 = (const float*)d_in[17];
    const float* ow0 = (const float*)d_in[18]; const float* ob0 = (const float*)d_in[19];
    const float* ow1 = (const float*)d_in[20]; const float* ob1 = (const float*)d_in[21];
    const float* ow2 = (const float*)d_in[22]; const float* ob2 = (const float*)d_in[23];
    const float* ow3 = (const float*)d_in[24]; const float* ob3 = (const float*)d_in[25];

    float* out = (float*)d_out;
    float* dxp = out;
    float* dxo = out + (long)B_*NP_*13;

    float* Anorm; cudaGetSymbolAddress((void**)&Anorm, g_Anorm);
    float* mobj;  cudaGetSymbolAddress((void**)&mobj,  g_mobj);
    float* objM;  cudaGetSymbolAddress((void**)&objM,  g_objM);
    __nv_bfloat16* W1h; cudaGetSymbolAddress((void**)&W1h, g_W1h);
    __nv_bfloat16* W1l; cudaGetSymbolAddress((void**)&W1l, g_W1l);

    k1_convert<<<(H_*H_ + 255)/256, 256>>>(ew1, W1h, W1l);
    k0_obj_prep<<<B_, NO_>>>(x_o, Anorm, objM, dxo);

    cudaFuncSetAttribute(k2_edge, cudaFuncAttributeMaxDynamicSharedMemorySize, K2_SMEM);
    k2_edge<<<B_*NO_, 256, K2_SMEM>>>(x_o, t, Anorm, ew0, eb0, W1h, W1l, eb1, ew2, eb2, mobj);

    k3_node<<<128, 256>>>(x_o, mobj, t,
                          vw0, vb0, vw1, vb1, vw2, vb2, vw3, vb3,
                          ow0, ob0, ow1, ob1, ow2, ob2, ow3, ob3,
                          dxo);

    size_t sm4 = (768 + PPB*SPAD) * sizeof(float);
    cudaFuncSetAttribute(k4_particles, cudaFuncAttributeMaxDynamicSharedMemorySize, (int)sm4);
    k4_particles<<<dim3(NP_/PPB, B_), 256, sm4>>>(x_p, S, objM, dxp);
}

// round 9
// speedup vs baseline: 1.9139x; 1.9139x over previous
#include <cuda_runtime.h>
#include <cuda_bf16.h>
#include <math.h>
#include <stdint.h>

#define B_   4
#define NO_  64
#define DO_  13
#define H_   256
#define NP_  32768

__device__ float g_mobjp[2*B_*NO_*DO_];   // per-half partial edge messages

__device__ __forceinline__ float gelu_exact(float x) {
    return 0.5f * x * (1.0f + erff(x * 0.7071067811865476f));
}
__device__ __forceinline__ void ffma2(unsigned long long& a,
                                      unsigned long long x,
                                      unsigned long long w) {
    asm("fma.rn.f32x2 %0, %1, %2, %0;" : "+l"(a) : "l"(x), "l"(w));
}
__device__ __forceinline__ unsigned long long pack2(float lo, float hi) {
    unsigned long long r;
    asm("mov.b64 %0, {%1, %2};" : "=l"(r) : "f"(lo), "f"(hi));
    return r;
}
__device__ __forceinline__ void unpack2(unsigned long long v, float& lo, float& hi) {
    asm("mov.b64 {%0, %1}, %2;" : "=f"(lo), "=f"(hi) : "l"(v));
}

// ---------------------------------------------------------------------------
// MEGA kernel: blocks [0,512) = edge-MLP blocks (node, half) — R5 layout;
//              blocks [512,1536) = particle blocks (128 particles each).
// block = 128 threads; dynamic smem 49408 B; 4 CTAs/SM.
// ---------------------------------------------------------------------------
#define HPAD 36
// edge smem layout (floats)
#define SM_XO    0       // 832
#define SM_EIN   832     // 31*36 = 1116
#define SM_AFULL 1948    // 64
#define SM_AROW  2012    // 32
#define SM_ASUM  2044    // 1 (+3 pad)
#define SM_H0    2048    // 256*36 = 9216
#define SM_RED   11264   // 4*256 = 1024
#define SM_RED2  12288   // 52
#define SM_TOTF  12352
#define MEGA_SMEM (SM_TOTF*4)   // 49408 B
// particle smem layout (floats): Ms[768], Ssm[128*36=4608]
#define PPB  128
#define SPAD 36

__global__ void __launch_bounds__(128, 4)
mega(const float* __restrict__ xo, const float* __restrict__ tptr,
     const float* __restrict__ W0, const float* __restrict__ b0,
     const float* __restrict__ W1, const float* __restrict__ b1,
     const float* __restrict__ W2, const float* __restrict__ b2,
     const float* __restrict__ xp, const float* __restrict__ S,
     float* __restrict__ mobjp, float* __restrict__ dxp) {
    extern __shared__ __align__(16) float sm[];
    int tid = threadIdx.x;

    if (blockIdx.x < 512) {
        // ================= EDGE BLOCK (R5 k2, Anorm computed in-block) ======
        float* xo_s = sm + SM_XO;
        float* einT = sm + SM_EIN;
        float* Afull= sm + SM_AFULL;
        float* Arow = sm + SM_AROW;
        float* asum = sm + SM_ASUM;
        float* h0T  = sm + SM_H0;
        float* red  = sm + SM_RED;
        float* red2 = sm + SM_RED2;

        int half = blockIdx.x & 1;
        int bi = blockIdx.x >> 1;
        int b = bi >> 6, i = bi & 63;

        const float* xb = xo + b*NO_*DO_;
        for (int idx = tid; idx < NO_*DO_; idx += 128) xo_s[idx] = xb[idx];
        __syncthreads();

        // adjacency row i (normalized), in-block
        if (tid < 64) {
            float dx = xo_s[i*13+0]-xo_s[tid*13+0];
            float dy = xo_s[i*13+1]-xo_s[tid*13+1];
            float dz = xo_s[i*13+2]-xo_s[tid*13+2];
            float d2 = dx*dx + dy*dy + dz*dz;
            Afull[tid] = (tid == i) ? 1.0f : expf(-d2 / 0.09f);
        }
        __syncthreads();
        if (tid < 32) {
            float s = Afull[tid] + Afull[tid + 32];
#pragma unroll
            for (int off = 16; off > 0; off >>= 1)
                s += __shfl_xor_sync(0xffffffffu, s, off);
            if (tid == 0) *asum = s;
        }
        __syncthreads();
        if (tid < 32) Arow[tid] = Afull[half*32 + tid] / (*asum);

        float t = *tptr;
        float xi0 = xo_s[i*13+0], xi1 = xo_s[i*13+1], xi2 = xo_s[i*13+2];
        for (int idx = tid; idx < 31*32; idx += 128) {
            int k = idx >> 5, e = idx & 31;
            int j = half*32 + e;
            float v;
            if (k < 13) v = xo_s[i*13 + k];
            else if (k < 26) v = xo_s[j*13 + (k-13)];
            else if (k < 29) v = xo_s[j*13 + (k-26)] - xo_s[i*13 + (k-26)];
            else if (k == 29) {
                float dx = xo_s[j*13+0]-xi0, dy = xo_s[j*13+1]-xi1, dz = xo_s[j*13+2]-xi2;
                v = sqrtf(dx*dx + dy*dy + dz*dz);
            } else v = t;
            einT[k*HPAD + e] = v;
        }
        __syncthreads();

        int ct = tid & 31;
        int e0 = (tid >> 5) * 8;
        int et = tid >> 5;

        unsigned long long acc2[32];

        // ---- layer 0: 31 -> 256 ----
        {
            unsigned long long bb2[4];
#pragma unroll
            for (int p = 0; p < 4; p++) bb2[p] = pack2(b0[ct + 64*p], b0[ct + 64*p + 32]);
#pragma unroll
            for (int e = 0; e < 8; e++)
#pragma unroll
                for (int p = 0; p < 4; p++) acc2[e*4+p] = bb2[p];

            for (int k = 0; k < 31; k++) {
                const float* wr = W0 + k*H_;
                unsigned long long w2[4];
#pragma unroll
                for (int p = 0; p < 4; p++) w2[p] = pack2(wr[ct + 64*p], wr[ct + 64*p + 32]);
                float4 a0 = *reinterpret_cast<const float4*>(&einT[k*HPAD + e0]);
                float4 a1 = *reinterpret_cast<const float4*>(&einT[k*HPAD + e0 + 4]);
                float av[8] = {a0.x,a0.y,a0.z,a0.w,a1.x,a1.y,a1.z,a1.w};
#pragma unroll
                for (int e = 0; e < 8; e++) {
                    unsigned long long s2 = pack2(av[e], av[e]);
#pragma unroll
                    for (int p = 0; p < 4; p++) ffma2(acc2[e*4+p], w2[p], s2);
                }
            }
#pragma unroll
            for (int e = 0; e < 8; e++)
#pragma unroll
                for (int p = 0; p < 4; p++) {
                    float lo, hi; unpack2(acc2[e*4+p], lo, hi);
                    h0T[(ct + 64*p)*HPAD + e0 + e]      = gelu_exact(lo);
                    h0T[(ct + 64*p + 32)*HPAD + e0 + e] = gelu_exact(hi);
                }
        }
        __syncthreads();

        // ---- layer 1: 256 -> 256 ----
        {
            unsigned long long bb2[4];
#pragma unroll
            for (int p = 0; p < 4; p++) bb2[p] = pack2(b1[ct + 64*p], b1[ct + 64*p + 32]);
#pragma unroll
            for (int e = 0; e < 8; e++)
#pragma unroll
                for (int p = 0; p < 4; p++) acc2[e*4+p] = bb2[p];

            for (int k = 0; k < 256; k++) {
                const float* wr = W1 + k*H_;
                unsigned long long w2[4];
#pragma unroll
                for (int p = 0; p < 4; p++) w2[p] = pack2(wr[ct + 64*p], wr[ct + 64*p + 32]);
                float4 a0 = *reinterpret_cast<const float4*>(&h0T[k*HPAD + e0]);
                float4 a1 = *reinterpret_cast<const float4*>(&h0T[k*HPAD + e0 + 4]);
                float av[8] = {a0.x,a0.y,a0.z,a0.w,a1.x,a1.y,a1.z,a1.w};
#pragma unroll
                for (int e = 0; e < 8; e++) {
                    unsigned long long s2 = pack2(av[e], av[e]);
#pragma unroll
                    for (int p = 0; p < 4; p++) ffma2(acc2[e*4+p], w2[p], s2);
                }
            }
        }

        // ---- gelu + A-weighted sum over this thread's 8 edges ----
        {
            float u[8];
#pragma unroll
            for (int q = 0; q < 8; q++) u[q] = 0.0f;
#pragma unroll
            for (int e = 0; e < 8; e++) {
                float ae = Arow[e0 + e];
#pragma unroll
                for (int p = 0; p < 4; p++) {
                    float lo, hi; unpack2(acc2[e*4+p], lo, hi);
                    u[2*p]   += ae * gelu_exact(lo);
                    u[2*p+1] += ae * gelu_exact(hi);
                }
            }
#pragma unroll
            for (int p = 0; p < 4; p++) {
                red[et*256 + ct + 64*p]      = u[2*p];
                red[et*256 + ct + 64*p + 32] = u[2*p+1];
            }
        }
        __syncthreads();

        // ---- combine 4 edge groups, project with W2 ----
        {
            int c1 = tid, c2 = tid + 128;
            float f1 = red[c1] + red[256+c1] + red[512+c1] + red[768+c1];
            float f2 = red[c2] + red[256+c2] + red[512+c2] + red[768+c2];
            float vd[13];
#pragma unroll
            for (int d = 0; d < 13; d++)
                vd[d] = f1 * W2[c1*13 + d] + f2 * W2[c2*13 + d];
#pragma unroll
            for (int off = 16; off > 0; off >>= 1)
#pragma unroll
                for (int d = 0; d < 13; d++) vd[d] += __shfl_down_sync(0xffffffffu, vd[d], off);
            int warp = tid >> 5, lane = tid & 31;
            if (lane == 0)
#pragma unroll
                for (int d = 0; d < 13; d++) red2[warp*13 + d] = vd[d];
        }
        __syncthreads();
        if (tid < 13) {
            float s = (half == 0) ? b2[tid] : 0.0f;
#pragma unroll
            for (int wp = 0; wp < 4; wp++) s += red2[wp*13 + tid];
            mobjp[half*(B_*NO_*DO_) + (b*NO_ + i)*13 + tid] = s;
        }
    } else {
        // ================= PARTICLE BLOCK ====================================
        float* Ms  = sm;          // 768
        float* Ssm = sm + 768;    // 128*36; reused for output staging

        int pid = blockIdx.x - 512;
        int b = pid >> 8;
        int n0 = (pid & 255) * PPB;

        // compute per-object affine map [c|M] from x_o (thread m < 64)
        if (tid < 64) {
            const float* xr = xo + (b*NO_ + tid)*DO_;
            float x0=xr[0], x1=xr[1], x2=xr[2], v0=xr[3], v1=xr[4], v2=xr[5];
            float w = xr[6], ux = xr[7], uy = xr[8], uz = xr[9];
            float ox = xr[10], oy = xr[11], oz = xr[12];
            float ss = w*w - (ux*ux + uy*uy + uz*uz);
            float R00 = ss + 2.0f*ux*ux,     R01 = 2.0f*(ux*uy - w*uz), R02 = 2.0f*(ux*uz + w*uy);
            float R10 = 2.0f*(ux*uy + w*uz), R11 = ss + 2.0f*uy*uy,     R12 = 2.0f*(uy*uz - w*ux);
            float R20 = 2.0f*(ux*uz - w*uy), R21 = 2.0f*(uy*uz + w*ux), R22 = ss + 2.0f*uz*uz;
            float M00 = -oz*R10 + oy*R20, M01 = -oz*R11 + oy*R21, M02 = -oz*R12 + oy*R22;
            float M10 =  oz*R00 - ox*R20, M11 =  oz*R01 - ox*R21, M12 =  oz*R02 - ox*R22;
            float M20 = -oy*R00 + ox*R10, M21 = -oy*R01 + ox*R11, M22 = -oy*R02 + ox*R12;
            float* om = Ms + tid*12;
            om[0] = v0 - (M00*x0 + M01*x1 + M02*x2);
            om[1] = v1 - (M10*x0 + M11*x1 + M12*x2);
            om[2] = v2 - (M20*x0 + M21*x1 + M22*x2);
            om[3]=M00; om[4]=M01; om[5]=M02;
            om[6]=M10; om[7]=M11; om[8]=M12;
            om[9]=M20; om[10]=M21; om[11]=M22;
        }

        int n = n0 + tid;
        const float* xr = xp + ((long)b*NP_ + n)*13;
        float px = xr[10], py = xr[11], pz = xr[12];
        float cvx = xr[3], cvy = xr[4], cvz = xr[5];

        unsigned long long acc2[6];
#pragma unroll
        for (int j = 0; j < 6; j++) acc2[j] = 0ull;

        const float* Sbase = S + ((long)b*NP_ + n0)*NO_;

        for (int c = 0; c < 2; c++) {
            __syncthreads();
            {
                const float4* src = reinterpret_cast<const float4*>(Sbase + c*32);
#pragma unroll
                for (int k = 0; k < 8; k++) {
                    int idx = k*128 + tid;
                    int p = idx >> 3, j = idx & 7;
                    float4 v = src[p*16 + j];
                    *reinterpret_cast<float4*>(&Ssm[p*SPAD + j*4]) = v;
                }
            }
            __syncthreads();

            const float4* srow = reinterpret_cast<const float4*>(&Ssm[tid*SPAD]);
#pragma unroll
            for (int m4 = 0; m4 < 8; m4++) {
                float4 s4 = srow[m4];
#pragma unroll
                for (int e = 0; e < 4; e++) {
                    int m = c*32 + m4*4 + e;
                    float s = (e==0) ? s4.x : (e==1) ? s4.y : (e==2) ? s4.z : s4.w;
                    unsigned long long s2v = pack2(s, s);
                    const ulonglong2* mr = reinterpret_cast<const ulonglong2*>(Ms + m*12);
                    ulonglong2 m0 = mr[0], m1 = mr[1], m2 = mr[2];
                    ffma2(acc2[0], m0.x, s2v); ffma2(acc2[1], m0.y, s2v);
                    ffma2(acc2[2], m1.x, s2v); ffma2(acc2[3], m1.y, s2v);
                    ffma2(acc2[4], m2.x, s2v); ffma2(acc2[5], m2.y, s2v);
                }
            }
        }

        float a0,a1,a2,a3,a4,a5,a6,a7,a8,a9,a10,a11;
        unpack2(acc2[0], a0, a1);  unpack2(acc2[1], a2, a3);
        unpack2(acc2[2], a4, a5);  unpack2(acc2[3], a6, a7);
        unpack2(acc2[4], a8, a9);  unpack2(acc2[5], a10, a11);
        float f0 = a0 + a3*px + a4*py + a5*pz;
        float f1 = a1 + a6*px + a7*py + a8*pz;
        float f2 = a2 + a9*px + a10*py + a11*pz;

        __syncthreads();
        float* orow = &Ssm[tid*13];
        orow[0] = f0; orow[1] = f1; orow[2] = f2;
        orow[3] = f0 - cvx; orow[4] = f1 - cvy; orow[5] = f2 - cvz;
#pragma unroll
        for (int d = 6; d < 13; d++) orow[d] = 0.0f;
        __syncthreads();

        float* og = dxp + ((long)b*NP_ + n0)*13;
        for (int idx = tid; idx < PPB*13; idx += 128) og[idx] = Ssm[idx];
    }
}

// ---------------------------------------------------------------------------
// K3: both node MLPs (27->256->256->256->3), 2 rows/block, grid = 256.
// Also writes dx_o cols [0:3] and [6:10] (mlp==0 blocks) — k0 absorbed.
// ---------------------------------------------------------------------------
__global__ void __launch_bounds__(256)
k3_node(const float* __restrict__ xo, const float* __restrict__ mobjp,
        const float* __restrict__ tptr,
        const float* __restrict__ vw0, const float* __restrict__ vb0,
        const float* __restrict__ vw1, const float* __restrict__ vb1,
        const float* __restrict__ vw2, const float* __restrict__ vb2,
        const float* __restrict__ vw3, const float* __restrict__ vb3,
        const float* __restrict__ ow0, const float* __restrict__ ob0,
        const float* __restrict__ ow1, const float* __restrict__ ob1,
        const float* __restrict__ ow2, const float* __restrict__ ob2,
        const float* __restrict__ ow3, const float* __restrict__ ob3,
        float* __restrict__ dxo) {
    __shared__ __align__(16) float inT[27*2];
    __shared__ __align__(16) float hA[256*2];
    __shared__ __align__(16) float hB[256*2];

    int tid = threadIdx.x;
    int grp = blockIdx.x & 31;
    int b   = (blockIdx.x >> 5) & 3;
    int mlp = blockIdx.x >> 7;
    int i0 = grp * 2;

    const float *W0, *B0, *W1, *B1, *W2, *B2, *W3, *B3;
    int col0;
    if (mlp == 0) { W0=vw0; B0=vb0; W1=vw1; B1=vb1; W2=vw2; B2=vb2; W3=vw3; B3=vb3; col0 = 3; }
    else          { W0=ow0; B0=ob0; W1=ow1; B1=ob1; W2=ow2; B2=ob2; W3=ow3; B3=ob3; col0 = 10; }

    float t = *tptr;
    if (tid < 54) {
        int k = tid >> 1, r = tid & 1;
        int row = b*NO_ + i0 + r;
        float v;
        if (k < 13) v = xo[row*13 + k];
        else if (k < 26) v = mobjp[row*13 + (k-13)] + mobjp[B_*NO_*DO_ + row*13 + (k-13)];
        else v = t;
        inT[k*2 + r] = v;
    }
    __syncthreads();

    unsigned long long acc2;
    float av0, av1;

    // layer 0: 27 -> 256, full unroll
    {
        float bb = B0[tid];
        acc2 = pack2(bb, bb);
#pragma unroll
        for (int k = 0; k < 27; k++) {
            float w = W0[k*H_ + tid];
            unsigned long long w2 = pack2(w, w);
            unsigned long long pq = *reinterpret_cast<const unsigned long long*>(&inT[k*2]);
            ffma2(acc2, pq, w2);
        }
        unpack2(acc2, av0, av1);
        hA[tid*2 + 0] = gelu_exact(av0);
        hA[tid*2 + 1] = gelu_exact(av1);
    }
    __syncthreads();

#define K3_LAYER256(W, BV, SRC, DST)                                           \
    {                                                                          \
        float bb = BV[tid];                                                    \
        acc2 = pack2(bb, bb);                                                  \
        for (int k0 = 0; k0 < 256; k0 += 16) {                                 \
            _Pragma("unroll")                                                  \
            for (int p = 0; p < 16; p++) {                                     \
                float w = W[(k0+p)*H_ + tid];                                  \
                unsigned long long w2 = pack2(w, w);                           \
                unsigned long long pq = *reinterpret_cast<const unsigned long long*>(&SRC[(k0+p)*2]); \
                ffma2(acc2, pq, w2);                                           \
            }                                                                  \
        }                                                                      \
        unpack2(acc2, av0, av1);                                               \
        DST[tid*2 + 0] = gelu_exact(av0);                                      \
        DST[tid*2 + 1] = gelu_exact(av1);                                      \
    }                                                                          \
    __syncthreads();

    K3_LAYER256(W1, B1, hA, hB)
    K3_LAYER256(W2, B2, hB, hA)

    // layer 3: 256 -> 3; warp wp (<2) handles local row wp
    {
        int wp = tid >> 5, lane = tid & 31;
        if (wp < 2) {
            float p0 = 0.0f, p1 = 0.0f, p2 = 0.0f;
#pragma unroll
            for (int k = lane; k < 256; k += 32) {
                float h = hA[k*2 + wp];
                p0 += h * W3[k*3 + 0];
                p1 += h * W3[k*3 + 1];
                p2 += h * W3[k*3 + 2];
            }
#pragma unroll
            for (int off = 16; off > 0; off >>= 1) {
                p0 += __shfl_down_sync(0xffffffffu, p0, off);
                p1 += __shfl_down_sync(0xffffffffu, p1, off);
                p2 += __shfl_down_sync(0xffffffffu, p2, off);
            }
            if (lane == 0) {
                int row = b*NO_ + i0 + wp;
                dxo[row*13 + col0 + 0] = p0 + B3[0];
                dxo[row*13 + col0 + 1] = p1 + B3[1];
                dxo[row*13 + col0 + 2] = p2 + B3[2];
            }
        }
    }

    // absorbed k0 output: vel (cols 0:3) and quaternion derivative (cols 6:10)
    if (mlp == 0 && tid < 2) {
        int row = b*NO_ + i0 + tid;
        const float* xr = xo + row*13;
        float* orow = dxo + row*13;
        orow[0] = xr[3]; orow[1] = xr[4]; orow[2] = xr[5];
        float qw = xr[6], qx = xr[7], qy = xr[8], qz = xr[9];
        float ox = xr[10], oy = xr[11], oz = xr[12];
        orow[6] = 0.5f * (-(ox*qx + oy*qy + oz*qz));
        orow[7] = 0.5f * ( ox*qw + oy*qz - oz*qy);
        orow[8] = 0.5f * (-ox*qz + oy*qw + oz*qx);
        orow[9] = 0.5f * ( ox*qy - oy*qx + oz*qw);
    }
}

// ---------------------------------------------------------------------------
extern "C" void kernel_launch(void* const* d_in, const int* in_sizes, int n_in,
                              void* d_out, int out_size) {
    const float* t   = (const float*)d_in[0];
    const float* x_p = (const float*)d_in[1];
    const float* x_o = (const float*)d_in[2];
    const float* S   = (const float*)d_in[3];
    const float* ew0 = (const float*)d_in[4];  const float* eb0 = (const float*)d_in[5];
    const float* ew1 = (const float*)d_in[6];  const float* eb1 = (const float*)d_in[7];
    const float* ew2 = (const float*)d_in[8];  const float* eb2 = (const float*)d_in[9];
    const float* vw0 = (const float*)d_in[10]; const float* vb0 = (const float*)d_in[11];
    const float* vw1 = (const float*)d_in[12]; const float* vb1 = (const float*)d_in[13];
    const float* vw2 = (const float*)d_in[14]; const float* vb2 = (const float*)d_in[15];
    const float* vw3 = (const float*)d_in[16]; const float* vb3 = (const float*)d_in[17];
    const float* ow0 = (const float*)d_in[18]; const float* ob0 = (const float*)d_in[19];
    const float* ow1 = (const float*)d_in[20]; const float* ob1 = (const float*)d_in[21];
    const float* ow2 = (const float*)d_in[22]; const float* ob2 = (const float*)d_in[23];
    const float* ow3 = (const float*)d_in[24]; const float* ob3 = (const float*)d_in[25];

    float* out = (float*)d_out;
    float* dxp = out;
    float* dxo = out + (long)B_*NP_*13;

    float* mobjp; cudaGetSymbolAddress((void**)&mobjp, g_mobjp);

    cudaFuncSetAttribute(mega, cudaFuncAttributeMaxDynamicSharedMemorySize, MEGA_SMEM);
    mega<<<512 + B_*(NP_/PPB), 128, MEGA_SMEM>>>(
        x_o, t, ew0, eb0, ew1, eb1, ew2, eb2, x_p, S, mobjp, dxp);

    k3_node<<<256, 256>>>(x_o, mobjp, t,
                          vw0, vb0, vw1, vb1, vw2, vb2, vw3, vb3,
                          ow0, ob0, ow1, ob1, ow2, ob2, ow3, ob3,
                          dxo);
}

// round 10
// speedup vs baseline: 2.0414x; 1.0666x over previous
#include <cuda_runtime.h>
#include <cuda_bf16.h>
#include <math.h>
#include <stdint.h>

#define B_   4
#define NO_  64
#define DO_  13
#define H_   256
#define NP_  32768

__device__ float g_mobjp[2*B_*NO_*DO_];   // per-half partial edge messages

__device__ __forceinline__ float gelu_exact(float x) {
    return 0.5f * x * (1.0f + erff(x * 0.7071067811865476f));
}
__device__ __forceinline__ void ffma2(unsigned long long& a,
                                      unsigned long long x,
                                      unsigned long long w) {
    asm("fma.rn.f32x2 %0, %1, %2, %0;" : "+l"(a) : "l"(x), "l"(w));
}
__device__ __forceinline__ unsigned long long pack2(float lo, float hi) {
    unsigned long long r;
    asm("mov.b64 %0, {%1, %2};" : "=l"(r) : "f"(lo), "f"(hi));
    return r;
}
__device__ __forceinline__ void unpack2(unsigned long long v, float& lo, float& hi) {
    asm("mov.b64 {%0, %1}, %2;" : "=f"(lo), "=f"(hi) : "l"(v));
}

// ---------------------------------------------------------------------------
// MEGA kernel (unchanged from R9 win): blocks [0,512) = edge-MLP (node, half);
// blocks [512,1536) = particle blocks (128 particles each).
// ---------------------------------------------------------------------------
#define HPAD 36
#define SM_XO    0
#define SM_EIN   832
#define SM_AFULL 1948
#define SM_AROW  2012
#define SM_ASUM  2044
#define SM_H0    2048
#define SM_RED   11264
#define SM_RED2  12288
#define SM_TOTF  12352
#define MEGA_SMEM (SM_TOTF*4)
#define PPB  128
#define SPAD 36

__global__ void __launch_bounds__(128, 4)
mega(const float* __restrict__ xo, const float* __restrict__ tptr,
     const float* __restrict__ W0, const float* __restrict__ b0,
     const float* __restrict__ W1, const float* __restrict__ b1,
     const float* __restrict__ W2, const float* __restrict__ b2,
     const float* __restrict__ xp, const float* __restrict__ S,
     float* __restrict__ mobjp, float* __restrict__ dxp) {
    extern __shared__ __align__(16) float sm[];
    int tid = threadIdx.x;

    if (blockIdx.x < 512) {
        float* xo_s = sm + SM_XO;
        float* einT = sm + SM_EIN;
        float* Afull= sm + SM_AFULL;
        float* Arow = sm + SM_AROW;
        float* asum = sm + SM_ASUM;
        float* h0T  = sm + SM_H0;
        float* red  = sm + SM_RED;
        float* red2 = sm + SM_RED2;

        int half = blockIdx.x & 1;
        int bi = blockIdx.x >> 1;
        int b = bi >> 6, i = bi & 63;

        const float* xb = xo + b*NO_*DO_;
        for (int idx = tid; idx < NO_*DO_; idx += 128) xo_s[idx] = xb[idx];
        __syncthreads();

        if (tid < 64) {
            float dx = xo_s[i*13+0]-xo_s[tid*13+0];
            float dy = xo_s[i*13+1]-xo_s[tid*13+1];
            float dz = xo_s[i*13+2]-xo_s[tid*13+2];
            float d2 = dx*dx + dy*dy + dz*dz;
            Afull[tid] = (tid == i) ? 1.0f : expf(-d2 / 0.09f);
        }
        __syncthreads();
        if (tid < 32) {
            float s = Afull[tid] + Afull[tid + 32];
#pragma unroll
            for (int off = 16; off > 0; off >>= 1)
                s += __shfl_xor_sync(0xffffffffu, s, off);
            if (tid == 0) *asum = s;
        }
        __syncthreads();
        if (tid < 32) Arow[tid] = Afull[half*32 + tid] / (*asum);

        float t = *tptr;
        float xi0 = xo_s[i*13+0], xi1 = xo_s[i*13+1], xi2 = xo_s[i*13+2];
        for (int idx = tid; idx < 31*32; idx += 128) {
            int k = idx >> 5, e = idx & 31;
            int j = half*32 + e;
            float v;
            if (k < 13) v = xo_s[i*13 + k];
            else if (k < 26) v = xo_s[j*13 + (k-13)];
            else if (k < 29) v = xo_s[j*13 + (k-26)] - xo_s[i*13 + (k-26)];
            else if (k == 29) {
                float dx = xo_s[j*13+0]-xi0, dy = xo_s[j*13+1]-xi1, dz = xo_s[j*13+2]-xi2;
                v = sqrtf(dx*dx + dy*dy + dz*dz);
            } else v = t;
            einT[k*HPAD + e] = v;
        }
        __syncthreads();

        int ct = tid & 31;
        int e0 = (tid >> 5) * 8;
        int et = tid >> 5;

        unsigned long long acc2[32];

        // ---- layer 0: 31 -> 256 ----
        {
            unsigned long long bb2[4];
#pragma unroll
            for (int p = 0; p < 4; p++) bb2[p] = pack2(b0[ct + 64*p], b0[ct + 64*p + 32]);
#pragma unroll
            for (int e = 0; e < 8; e++)
#pragma unroll
                for (int p = 0; p < 4; p++) acc2[e*4+p] = bb2[p];

            for (int k = 0; k < 31; k++) {
                const float* wr = W0 + k*H_;
                unsigned long long w2[4];
#pragma unroll
                for (int p = 0; p < 4; p++) w2[p] = pack2(wr[ct + 64*p], wr[ct + 64*p + 32]);
                float4 a0 = *reinterpret_cast<const float4*>(&einT[k*HPAD + e0]);
                float4 a1 = *reinterpret_cast<const float4*>(&einT[k*HPAD + e0 + 4]);
                float av[8] = {a0.x,a0.y,a0.z,a0.w,a1.x,a1.y,a1.z,a1.w};
#pragma unroll
                for (int e = 0; e < 8; e++) {
                    unsigned long long s2 = pack2(av[e], av[e]);
#pragma unroll
                    for (int p = 0; p < 4; p++) ffma2(acc2[e*4+p], w2[p], s2);
                }
            }
#pragma unroll
            for (int e = 0; e < 8; e++)
#pragma unroll
                for (int p = 0; p < 4; p++) {
                    float lo, hi; unpack2(acc2[e*4+p], lo, hi);
                    h0T[(ct + 64*p)*HPAD + e0 + e]      = gelu_exact(lo);
                    h0T[(ct + 64*p + 32)*HPAD + e0 + e] = gelu_exact(hi);
                }
        }
        __syncthreads();

        // ---- layer 1: 256 -> 256 ----
        {
            unsigned long long bb2[4];
#pragma unroll
            for (int p = 0; p < 4; p++) bb2[p] = pack2(b1[ct + 64*p], b1[ct + 64*p + 32]);
#pragma unroll
            for (int e = 0; e < 8; e++)
#pragma unroll
                for (int p = 0; p < 4; p++) acc2[e*4+p] = bb2[p];

            for (int k = 0; k < 256; k++) {
                const float* wr = W1 + k*H_;
                unsigned long long w2[4];
#pragma unroll
                for (int p = 0; p < 4; p++) w2[p] = pack2(wr[ct + 64*p], wr[ct + 64*p + 32]);
                float4 a0 = *reinterpret_cast<const float4*>(&h0T[k*HPAD + e0]);
                float4 a1 = *reinterpret_cast<const float4*>(&h0T[k*HPAD + e0 + 4]);
                float av[8] = {a0.x,a0.y,a0.z,a0.w,a1.x,a1.y,a1.z,a1.w};
#pragma unroll
                for (int e = 0; e < 8; e++) {
                    unsigned long long s2 = pack2(av[e], av[e]);
#pragma unroll
                    for (int p = 0; p < 4; p++) ffma2(acc2[e*4+p], w2[p], s2);
                }
            }
        }

        // ---- gelu + A-weighted sum over this thread's 8 edges ----
        {
            float u[8];
#pragma unroll
            for (int q = 0; q < 8; q++) u[q] = 0.0f;
#pragma unroll
            for (int e = 0; e < 8; e++) {
                float ae = Arow[e0 + e];
#pragma unroll
                for (int p = 0; p < 4; p++) {
                    float lo, hi; unpack2(acc2[e*4+p], lo, hi);
                    u[2*p]   += ae * gelu_exact(lo);
                    u[2*p+1] += ae * gelu_exact(hi);
                }
            }
#pragma unroll
            for (int p = 0; p < 4; p++) {
                red[et*256 + ct + 64*p]      = u[2*p];
                red[et*256 + ct + 64*p + 32] = u[2*p+1];
            }
        }
        __syncthreads();

        {
            int c1 = tid, c2 = tid + 128;
            float f1 = red[c1] + red[256+c1] + red[512+c1] + red[768+c1];
            float f2 = red[c2] + red[256+c2] + red[512+c2] + red[768+c2];
            float vd[13];
#pragma unroll
            for (int d = 0; d < 13; d++)
                vd[d] = f1 * W2[c1*13 + d] + f2 * W2[c2*13 + d];
#pragma unroll
            for (int off = 16; off > 0; off >>= 1)
#pragma unroll
                for (int d = 0; d < 13; d++) vd[d] += __shfl_down_sync(0xffffffffu, vd[d], off);
            int warp = tid >> 5, lane = tid & 31;
            if (lane == 0)
#pragma unroll
                for (int d = 0; d < 13; d++) red2[warp*13 + d] = vd[d];
        }
        __syncthreads();
        if (tid < 13) {
            float s = (half == 0) ? b2[tid] : 0.0f;
#pragma unroll
            for (int wp = 0; wp < 4; wp++) s += red2[wp*13 + tid];
            mobjp[half*(B_*NO_*DO_) + (b*NO_ + i)*13 + tid] = s;
        }
    } else {
        // ================= PARTICLE BLOCK ====================================
        float* Ms  = sm;
        float* Ssm = sm + 768;

        int pid = blockIdx.x - 512;
        int b = pid >> 8;
        int n0 = (pid & 255) * PPB;

        if (tid < 64) {
            const float* xr = xo + (b*NO_ + tid)*DO_;
            float x0=xr[0], x1=xr[1], x2=xr[2], v0=xr[3], v1=xr[4], v2=xr[5];
            float w = xr[6], ux = xr[7], uy = xr[8], uz = xr[9];
            float ox = xr[10], oy = xr[11], oz = xr[12];
            float ss = w*w - (ux*ux + uy*uy + uz*uz);
            float R00 = ss + 2.0f*ux*ux,     R01 = 2.0f*(ux*uy - w*uz), R02 = 2.0f*(ux*uz + w*uy);
            float R10 = 2.0f*(ux*uy + w*uz), R11 = ss + 2.0f*uy*uy,     R12 = 2.0f*(uy*uz - w*ux);
            float R20 = 2.0f*(ux*uz - w*uy), R21 = 2.0f*(uy*uz + w*ux), R22 = ss + 2.0f*uz*uz;
            float M00 = -oz*R10 + oy*R20, M01 = -oz*R11 + oy*R21, M02 = -oz*R12 + oy*R22;
            float M10 =  oz*R00 - ox*R20, M11 =  oz*R01 - ox*R21, M12 =  oz*R02 - ox*R22;
            float M20 = -oy*R00 + ox*R10, M21 = -oy*R01 + ox*R11, M22 = -oy*R02 + ox*R12;
            float* om = Ms + tid*12;
            om[0] = v0 - (M00*x0 + M01*x1 + M02*x2);
            om[1] = v1 - (M10*x0 + M11*x1 + M12*x2);
            om[2] = v2 - (M20*x0 + M21*x1 + M22*x2);
            om[3]=M00; om[4]=M01; om[5]=M02;
            om[6]=M10; om[7]=M11; om[8]=M12;
            om[9]=M20; om[10]=M21; om[11]=M22;
        }

        int n = n0 + tid;
        const float* xr = xp + ((long)b*NP_ + n)*13;
        float px = xr[10], py = xr[11], pz = xr[12];
        float cvx = xr[3], cvy = xr[4], cvz = xr[5];

        unsigned long long acc2[6];
#pragma unroll
        for (int j = 0; j < 6; j++) acc2[j] = 0ull;

        const float* Sbase = S + ((long)b*NP_ + n0)*NO_;

        for (int c = 0; c < 2; c++) {
            __syncthreads();
            {
                const float4* src = reinterpret_cast<const float4*>(Sbase + c*32);
#pragma unroll
                for (int k = 0; k < 8; k++) {
                    int idx = k*128 + tid;
                    int p = idx >> 3, j = idx & 7;
                    float4 v = src[p*16 + j];
                    *reinterpret_cast<float4*>(&Ssm[p*SPAD + j*4]) = v;
                }
            }
            __syncthreads();

            const float4* srow = reinterpret_cast<const float4*>(&Ssm[tid*SPAD]);
#pragma unroll
            for (int m4 = 0; m4 < 8; m4++) {
                float4 s4 = srow[m4];
#pragma unroll
                for (int e = 0; e < 4; e++) {
                    int m = c*32 + m4*4 + e;
                    float s = (e==0) ? s4.x : (e==1) ? s4.y : (e==2) ? s4.z : s4.w;
                    unsigned long long s2v = pack2(s, s);
                    const ulonglong2* mr = reinterpret_cast<const ulonglong2*>(Ms + m*12);
                    ulonglong2 m0 = mr[0], m1 = mr[1], m2 = mr[2];
                    ffma2(acc2[0], m0.x, s2v); ffma2(acc2[1], m0.y, s2v);
                    ffma2(acc2[2], m1.x, s2v); ffma2(acc2[3], m1.y, s2v);
                    ffma2(acc2[4], m2.x, s2v); ffma2(acc2[5], m2.y, s2v);
                }
            }
        }

        float a0,a1,a2,a3,a4,a5,a6,a7,a8,a9,a10,a11;
        unpack2(acc2[0], a0, a1);  unpack2(acc2[1], a2, a3);
        unpack2(acc2[2], a4, a5);  unpack2(acc2[3], a6, a7);
        unpack2(acc2[4], a8, a9);  unpack2(acc2[5], a10, a11);
        float f0 = a0 + a3*px + a4*py + a5*pz;
        float f1 = a1 + a6*px + a7*py + a8*pz;
        float f2 = a2 + a9*px + a10*py + a11*pz;

        __syncthreads();
        float* orow = &Ssm[tid*13];
        orow[0] = f0; orow[1] = f1; orow[2] = f2;
        orow[3] = f0 - cvx; orow[4] = f1 - cvy; orow[5] = f2 - cvz;
#pragma unroll
        for (int d = 6; d < 13; d++) orow[d] = 0.0f;
        __syncthreads();

        float* og = dxp + ((long)b*NP_ + n0)*13;
        for (int idx = tid; idx < PPB*13; idx += 128) og[idx] = Ssm[idx];
    }
}

// ---------------------------------------------------------------------------
// K3: node MLPs with K split across 4 sub-groups.  Block = 1024 threads:
// thread = (channel c = tid&255, K-slice q = tid>>8).  4 rows per block.
// grid = 128 (2 mlps x 4 b x 16 rowgroups).  Serial weight chain per layer
// drops from 256 to 64 loads.
// ---------------------------------------------------------------------------
__global__ void __launch_bounds__(1024)
k3_node(const float* __restrict__ xo, const float* __restrict__ mobjp,
        const float* __restrict__ tptr,
        const float* __restrict__ vw0, const float* __restrict__ vb0,
        const float* __restrict__ vw1, const float* __restrict__ vb1,
        const float* __restrict__ vw2, const float* __restrict__ vb2,
        const float* __restrict__ vw3, const float* __restrict__ vb3,
        const float* __restrict__ ow0, const float* __restrict__ ob0,
        const float* __restrict__ ow1, const float* __restrict__ ob1,
        const float* __restrict__ ow2, const float* __restrict__ ob2,
        const float* __restrict__ ow3, const float* __restrict__ ob3,
        float* __restrict__ dxo) {
    __shared__ __align__(16) float inT[27*4];
    __shared__ __align__(16) float hA[256*4];
    __shared__ __align__(16) float hB[256*4];
    __shared__ __align__(16) float part[4*256*4];

    int tid = threadIdx.x;
    int c = tid & 255, q = tid >> 8;
    int mlp = blockIdx.x >> 6;
    int rem = blockIdx.x & 63;
    int b = rem >> 4, grp = rem & 15;
    int i0 = grp * 4;

    const float *W0, *B0, *W1, *B1, *W2, *B2, *W3, *B3;
    int col0;
    if (mlp == 0) { W0=vw0; B0=vb0; W1=vw1; B1=vb1; W2=vw2; B2=vb2; W3=vw3; B3=vb3; col0 = 3; }
    else          { W0=ow0; B0=ob0; W1=ow1; B1=ob1; W2=ow2; B2=ob2; W3=ow3; B3=ob3; col0 = 10; }

    float t = *tptr;
    if (tid < 108) {
        int k = tid >> 2, r = tid & 3;
        int row = b*NO_ + i0 + r;
        float v;
        if (k < 13) v = xo[row*13 + k];
        else if (k < 26) v = mobjp[row*13 + (k-13)] + mobjp[B_*NO_*DO_ + row*13 + (k-13)];
        else v = t;
        inT[k*4 + r] = v;
    }
    __syncthreads();

    // layer 0: 27 -> 256 (q==0 only; short chain)
    if (q == 0) {
        float bb = B0[c];
        unsigned long long a0 = pack2(bb, bb), a1 = a0;
#pragma unroll
        for (int k = 0; k < 27; k++) {
            float w = W0[k*H_ + c];
            unsigned long long w2 = pack2(w, w);
            ulonglong2 pq = *reinterpret_cast<const ulonglong2*>(&inT[k*4]);
            ffma2(a0, pq.x, w2);
            ffma2(a1, pq.y, w2);
        }
        float v0,v1,v2,v3; unpack2(a0,v0,v1); unpack2(a1,v2,v3);
        hA[c*4+0]=gelu_exact(v0); hA[c*4+1]=gelu_exact(v1);
        hA[c*4+2]=gelu_exact(v2); hA[c*4+3]=gelu_exact(v3);
    }
    __syncthreads();

#define K3_LAYER_KS(W, BV, SRC, DST)                                           \
    {                                                                          \
        unsigned long long a0, a1;                                             \
        if (q == 0) { float bb = BV[c]; a0 = pack2(bb, bb); a1 = a0; }         \
        else { a0 = 0ull; a1 = 0ull; }                                         \
        int kbase = q * 64;                                                    \
        _Pragma("unroll 16")                                                   \
        for (int kk = 0; kk < 64; kk++) {                                      \
            int k = kbase + kk;                                                \
            float w = W[k*H_ + c];                                             \
            unsigned long long w2 = pack2(w, w);                               \
            ulonglong2 pq = *reinterpret_cast<const ulonglong2*>(&SRC[k*4]);   \
            ffma2(a0, pq.x, w2);                                               \
            ffma2(a1, pq.y, w2);                                               \
        }                                                                      \
        float v0,v1,v2,v3; unpack2(a0,v0,v1); unpack2(a1,v2,v3);               \
        float4 pv = make_float4(v0, v1, v2, v3);                               \
        *reinterpret_cast<float4*>(&part[q*1024 + c*4]) = pv;                  \
        __syncthreads();                                                       \
        if (q == 0) {                                                          \
            float4 p0 = *reinterpret_cast<const float4*>(&part[c*4]);          \
            float4 p1 = *reinterpret_cast<const float4*>(&part[1024 + c*4]);   \
            float4 p2 = *reinterpret_cast<const float4*>(&part[2048 + c*4]);   \
            float4 p3 = *reinterpret_cast<const float4*>(&part[3072 + c*4]);   \
            DST[c*4+0] = gelu_exact(p0.x + p1.x + p2.x + p3.x);                \
            DST[c*4+1] = gelu_exact(p0.y + p1.y + p2.y + p3.y);                \
            DST[c*4+2] = gelu_exact(p0.z + p1.z + p2.z + p3.z);                \
            DST[c*4+3] = gelu_exact(p0.w + p1.w + p2.w + p3.w);                \
        }                                                                      \
        __syncthreads();                                                       \
    }

    K3_LAYER_KS(W1, B1, hA, hB)
    K3_LAYER_KS(W2, B2, hB, hA)

    // layer 3: 256 -> 3; warps 0-3 handle local rows 0-3
    {
        int wp = tid >> 5, lane = tid & 31;
        if (wp < 4) {
            float p0 = 0.0f, p1 = 0.0f, p2 = 0.0f;
#pragma unroll
            for (int k = lane; k < 256; k += 32) {
                float h = hA[k*4 + wp];
                p0 += h * W3[k*3 + 0];
                p1 += h * W3[k*3 + 1];
                p2 += h * W3[k*3 + 2];
            }
#pragma unroll
            for (int off = 16; off > 0; off >>= 1) {
                p0 += __shfl_down_sync(0xffffffffu, p0, off);
                p1 += __shfl_down_sync(0xffffffffu, p1, off);
                p2 += __shfl_down_sync(0xffffffffu, p2, off);
            }
            if (lane == 0) {
                int row = b*NO_ + i0 + wp;
                dxo[row*13 + col0 + 0] = p0 + B3[0];
                dxo[row*13 + col0 + 1] = p1 + B3[1];
                dxo[row*13 + col0 + 2] = p2 + B3[2];
            }
        }
    }

    // absorbed k0 output: vel (cols 0:3) and quaternion derivative (cols 6:10)
    if (mlp == 0 && tid < 4) {
        int row = b*NO_ + i0 + tid;
        const float* xr = xo + row*13;
        float* orow = dxo + row*13;
        orow[0] = xr[3]; orow[1] = xr[4]; orow[2] = xr[5];
        float qw = xr[6], qx = xr[7], qy = xr[8], qz = xr[9];
        float ox = xr[10], oy = xr[11], oz = xr[12];
        orow[6] = 0.5f * (-(ox*qx + oy*qy + oz*qz));
        orow[7] = 0.5f * ( ox*qw + oy*qz - oz*qy);
        orow[8] = 0.5f * (-ox*qz + oy*qw + oz*qx);
        orow[9] = 0.5f * ( ox*qy - oy*qx + oz*qw);
    }
}

// ---------------------------------------------------------------------------
extern "C" void kernel_launch(void* const* d_in, const int* in_sizes, int n_in,
                              void* d_out, int out_size) {
    const float* t   = (const float*)d_in[0];
    const float* x_p = (const float*)d_in[1];
    const float* x_o = (const float*)d_in[2];
    const float* S   = (const float*)d_in[3];
    const float* ew0 = (const float*)d_in[4];  const float* eb0 = (const float*)d_in[5];
    const float* ew1 = (const float*)d_in[6];  const float* eb1 = (const float*)d_in[7];
    const float* ew2 = (const float*)d_in[8];  const float* eb2 = (const float*)d_in[9];
    const float* vw0 = (const float*)d_in[10]; const float* vb0 = (const float*)d_in[11];
    const float* vw1 = (const float*)d_in[12]; const float* vb1 = (const float*)d_in[13];
    const float* vw2 = (const float*)d_in[14]; const float* vb2 = (const float*)d_in[15];
    const float* vw3 = (const float*)d_in[16]; const float* vb3 = (const float*)d_in[17];
    const float* ow0 = (const float*)d_in[18]; const float* ob0 = (const float*)d_in[19];
    const float* ow1 = (const float*)d_in[20]; const float* ob1 = (const float*)d_in[21];
    const float* ow2 = (const float*)d_in[22]; const float* ob2 = (const float*)d_in[23];
    const float* ow3 = (const float*)d_in[24]; const float* ob3 = (const float*)d_in[25];

    float* out = (float*)d_out;
    float* dxp = out;
    float* dxo = out + (long)B_*NP_*13;

    float* mobjp; cudaGetSymbolAddress((void**)&mobjp, g_mobjp);

    cudaFuncSetAttribute(mega, cudaFuncAttributeMaxDynamicSharedMemorySize, MEGA_SMEM);
    mega<<<512 + B_*(NP_/PPB), 128, MEGA_SMEM>>>(
        x_o, t, ew0, eb0, ew1, eb1, ew2, eb2, x_p, S, mobjp, dxp);

    k3_node<<<128, 1024>>>(x_o, mobjp, t,
                           vw0, vb0, vw1, vb1, vw2, vb2, vw3, vb3,
                           ow0, ob0, ow1, ob1, ow2, ob2, ow3, ob3,
                           dxo);
}